// round 4
// baseline (speedup 1.0000x reference)
#include <cuda_runtime.h>

// Reference semantics after dead-code elimination:
//   r  = eye(3)                       (unconditional overwrite in reference)
//   tb = -mean(mkpts0, axis=1)        ( = -r @ src_mean with r = I )
// Output: 12 floats = [r row-major (9), tb (3)].
//
// Inputs (metadata order): mkpts0 [3,8192] f32, mkpts1 [3,8192] f32 (unused),
// valid_scores [8192,8192] f32 (unused).

#define ROWLEN   8192
#define TPB      1024
#define NWARPS   (TPB / 32)          // 32
#define INV_NEG  (-1.0f / 8192.0f)   // exact: power-of-two divisor

__global__ void __launch_bounds__(TPB, 1)
svdhead_kernel(const float* __restrict__ mkpts0, float* __restrict__ out) {
    const int b = blockIdx.x;       // row 0..2
    const int t = threadIdx.x;

    // Issue the two LDG.128 FIRST so the DRAM round trip starts immediately;
    // 1024 threads x 2 float4 = 2048 loads in flight, one round trip total.
    const float4* row4 = reinterpret_cast<const float4*>(mkpts0)
                       + (size_t)b * (ROWLEN / 4);
    float4 v0 = row4[t];
    float4 v1 = row4[t + TPB];

    // Identity write overlaps the load latency (block 0, indices 0..8).
    if (b == 0 && t < 9) {
        out[t] = ((t & 3) == 0) ? 1.0f : 0.0f;   // t = 0,4,8 -> 1
    }

    // Depth-3 pairwise add tree over the 8 scalars.
    float sum = ((v0.x + v0.y) + (v0.z + v0.w)) + ((v1.x + v1.y) + (v1.z + v1.w));

    // Warp tree reduce: 5 shfl.
    #pragma unroll
    for (int off = 16; off > 0; off >>= 1)
        sum += __shfl_xor_sync(0xFFFFFFFFu, sum, off);

    __shared__ float warp_sums[NWARPS];
    if ((t & 31) == 0) warp_sums[t >> 5] = sum;
    __syncthreads();

    // First warp folds the 32 warp sums: 1 LDS + 5 shfl + 1 STG.
    if (t < 32) {
        float s = warp_sums[t];
        #pragma unroll
        for (int off = 16; off > 0; off >>= 1)
            s += __shfl_xor_sync(0xFFFFFFFFu, s, off);
        if (t == 0)
            out[9 + b] = s * INV_NEG;
    }
}

extern "C" void kernel_launch(void* const* d_in, const int* in_sizes, int n_in,
                              void* d_out, int out_size) {
    const float* mkpts0 = (const float*)d_in[0];
    float* out = (float*)d_out;
    svdhead_kernel<<<3, TPB>>>(mkpts0, out);
}